// round 14
// baseline (speedup 1.0000x reference)
#include <cuda_runtime.h>
#include <cuda_fp16.h>
#include <cstdint>
#include <math.h>

#define B_    8192
#define OBSD  256
#define ACTD  32
#define HIDD  512
#define PEXP  8

// ======================= scratch (no allocs allowed) =======================
__device__ __align__(16) __half d_obs16[B_ * OBSD];
__device__ __align__(16) __half d_gw016[HIDD * OBSD];
__device__ __align__(16) __half d_gw116[HIDD * HIDD];
__device__ __align__(16) __half d_ew016[PEXP * HIDD * OBSD];
__device__ __align__(16) __half d_ew116[PEXP * HIDD * HIDD];
__device__ __align__(16) __half d_ew216[PEXP * 2 * ACTD * HIDD];
__device__ __align__(16) __half d_act0[B_ * HIDD];
__device__ __align__(16) __half d_actA[B_ * HIDD];
__device__ __align__(16) __half d_actB[B_ * HIDD];
__device__ __align__(16) float d_partbuf[8 * B_ * PEXP];
__device__ __align__(16) float d_blend[B_ * PEXP];

// ======================= low-level helpers =================================
__device__ __forceinline__ uint32_t smem_u32(const void* p) {
    uint32_t a;
    asm("{ .reg .u64 t; cvta.to.shared.u64 t, %1; cvt.u32.u64 %0, t; }" : "=r"(a) : "l"(p));
    return a;
}
#define CP_ASYNC16(dst, src) \
    asm volatile("cp.async.cg.shared.global [%0], [%1], 16;" :: "r"(dst), "l"(src))
#define CP_COMMIT() asm volatile("cp.async.commit_group;" ::: "memory")
#define CP_WAIT_1() asm volatile("cp.async.wait_group 1;" ::: "memory")

__device__ __forceinline__ void ldsm4(uint32_t* r, uint32_t addr) {
    asm volatile("ldmatrix.sync.aligned.m8n8.x4.shared.b16 {%0,%1,%2,%3}, [%4];"
                 : "=r"(r[0]), "=r"(r[1]), "=r"(r[2]), "=r"(r[3]) : "r"(addr));
}
__device__ __forceinline__ void mma16816(float* c, const uint32_t* a, uint32_t b0, uint32_t b1) {
    asm volatile(
        "mma.sync.aligned.m16n8k16.row.col.f32.f16.f16.f32 "
        "{%0,%1,%2,%3}, {%4,%5,%6,%7}, {%8,%9}, {%0,%1,%2,%3};"
        : "+f"(c[0]), "+f"(c[1]), "+f"(c[2]), "+f"(c[3])
        : "r"(a[0]), "r"(a[1]), "r"(a[2]), "r"(a[3]), "r"(b0), "r"(b1));
}
__device__ __forceinline__ uint32_t hmul2u(uint32_t a, uint32_t b) {
    uint32_t r;
    asm("mul.rn.f16x2 %0, %1, %2;" : "=r"(r) : "r"(a), "r"(b));
    return r;
}

// ======================= batched fp32 -> fp16 convert ======================
struct CvtArgs {
    const float* src[6];
    __half*      dst[6];
    int          end[6];   // prefix-sum ends, in float4 units
};

__global__ __launch_bounds__(256)
void cvt_all(CvtArgs a, int total4) {
    int i = blockIdx.x * blockDim.x + threadIdx.x;
    const int stride = gridDim.x * blockDim.x;
    for (; i < total4; i += stride) {
        int seg = 0;
#pragma unroll
        for (int k = 0; k < 5; k++) seg += (i >= a.end[k]) ? 1 : 0;
        const int base = (seg == 0) ? 0 : a.end[seg - 1];
        const int off = i - base;
        const float4 v = *(const float4*)(a.src[seg] + (size_t)off * 4);
        __half2 h0 = __floats2half2_rn(v.x, v.y);
        __half2 h1 = __floats2half2_rn(v.z, v.w);
        *(uint2*)(a.dst[seg] + (size_t)off * 4) = make_uint2(*(uint32_t*)&h0, *(uint32_t*)&h1);
    }
}

// ======================= fp16 blended MoE GEMM =============================
// EPI 0: relu -> fp16 store.  EPI 2: relu, NO Y store; gate-logit partials.
template <int NEXP, int EPI, int BM, int BN, int K>
__global__ __launch_bounds__(256, 2)
void moe_gemm(const __half* __restrict__ A, const __half* __restrict__ W,
              const float* __restrict__ bias, const float* __restrict__ blend,
              const float* __restrict__ gw2, float* __restrict__ partOut,
              __half* __restrict__ Yh, float* __restrict__ Yf, int NTOT)
{
    constexpr int NCK   = K / 64;
    constexpr int NCH   = NEXP * NCK;
    constexpr int MT    = BM / 64;
    constexpr int NT    = BN / 32;
    constexpr int AIT   = BM / 32;
    constexpr int BIT_  = BN / 32;
    constexpr int STAGE = BM * 128 + BN * 128;

    extern __shared__ __align__(16) char smem[];
    float* bias_s  = (float*)smem;           // [NEXP*BN]
    float* blend_s = (float*)(smem + 4096);  // [BM*8]  (EPI2: gw2 slice [8][128])
    const uint32_t sb = smem_u32(smem);

    const int tid = threadIdx.x;
    const int wid = tid >> 5;
    const int t   = tid & 31;
    const int row0 = blockIdx.y * BM;
    const int n0   = blockIdx.x * BN;

    for (int i = tid; i < NEXP * BN; i += 256)
        bias_s[i] = bias[(size_t)(i / BN) * NTOT + n0 + (i % BN)];
    if (NEXP > 1)
        for (int i = tid; i < BM * 8; i += 256)
            blend_s[i] = blend[(size_t)(row0 + (i >> 3)) * PEXP + (i & 7)];
    if (EPI == 2)
        for (int i = tid; i < PEXP * BN; i += 256)
            blend_s[i] = gw2[(size_t)(i >> 7) * HIDD + n0 + (i & 127)];
    __syncthreads();

    const int wm = wid >> 1, wn = wid & 1;
    const int aro = t & 15;
    const int akg = t >> 4;
    const int bno = ((t >> 4) << 3) + (t & 7);
    const int bkg = (t >> 3) & 1;
    const int tq  = t >> 2, tr = t & 3;

    float acc[MT][2 * NT][4];
#pragma unroll
    for (int a = 0; a < MT; a++)
#pragma unroll
        for (int b = 0; b < 2 * NT; b++)
#pragma unroll
            for (int q = 0; q < 4; q++) acc[a][b][q] = 0.0f;

    uint4 areg[AIT];

    auto ldgA = [&](int ci) {
        const int kk = (ci % NCK) * 64;
#pragma unroll
        for (int it = 0; it < AIT; it++) {
            const int idx = tid + it * 256;
            const int r = idx >> 3, ch = idx & 7;
            areg[it] = *(const uint4*)(A + (size_t)(row0 + r) * K + kk + ch * 8);
        }
    };
    auto stsA = [&](int ci) {
        const int p = ci / NCK;
        const int s = ci % 3;
        const uint32_t off0 = 8192 + (uint32_t)s * STAGE;
#pragma unroll
        for (int it = 0; it < AIT; it++) {
            const int idx = tid + it * 256;
            const int r = idx >> 3, ch = idx & 7;
            uint4 v = areg[it];
            const __half hb = __float2half(blend_s[r * 8 + p]);
            __half2 hb2 = __half2half2(hb);
            const uint32_t b2 = *(uint32_t*)&hb2;
            v.x = hmul2u(v.x, b2);  v.y = hmul2u(v.y, b2);
            v.z = hmul2u(v.z, b2);  v.w = hmul2u(v.w, b2);
            *(uint4*)(smem + off0 + r * 128 + ((ch ^ (r & 7)) << 4)) = v;
        }
    };
    auto cpA = [&](int ci) {
        const int kk = (ci % NCK) * 64;
        const int s  = ci % 3;
        const uint32_t stA = sb + 8192 + (uint32_t)s * STAGE;
#pragma unroll
        for (int it = 0; it < AIT; it++) {
            const int idx = tid + it * 256;
            const int r = idx >> 3, ch = idx & 7;
            const __half* src = A + (size_t)(row0 + r) * K + kk + ch * 8;
            CP_ASYNC16(stA + r * 128 + ((ch ^ (r & 7)) << 4), src);
        }
    };
    auto cpB = [&](int ci) {
        const int p  = ci / NCK;
        const int kk = (ci % NCK) * 64;
        const int s  = ci % 3;
        const uint32_t stB = sb + 8192 + (uint32_t)s * STAGE + BM * 128;
#pragma unroll
        for (int it = 0; it < BIT_; it++) {
            const int idx = tid + it * 256;
            const int r = idx >> 3, ch = idx & 7;
            const __half* src = W + ((size_t)p * NTOT + n0 + r) * K + kk + ch * 8;
            CP_ASYNC16(stB + r * 128 + ((ch ^ (r & 7)) << 4), src);
        }
    };

    auto mmaStage = [&](int s) {
        const uint32_t stA = sb + 8192 + (uint32_t)s * STAGE;
        const uint32_t stB = stA + BM * 128;
#pragma unroll
        for (int kc = 0; kc < 4; kc++) {
            uint32_t a[MT][4];
#pragma unroll
            for (int mt = 0; mt < MT; mt++) {
                const int row = wm * (MT * 16) + mt * 16 + aro;
                const int ch = kc * 2 + akg;
                ldsm4(a[mt], stA + row * 128 + ((ch ^ (row & 7)) << 4));
            }
            uint32_t b[NT][4];
#pragma unroll
            for (int nt = 0; nt < NT; nt++) {
                const int n = wn * (NT * 16) + nt * 16 + bno;
                const int ch = kc * 2 + bkg;
                ldsm4(b[nt], stB + n * 128 + ((ch ^ (n & 7)) << 4));
            }
#pragma unroll
            for (int mt = 0; mt < MT; mt++)
#pragma unroll
                for (int nt = 0; nt < NT; nt++) {
                    mma16816(acc[mt][2 * nt + 0], a[mt], b[nt][0], b[nt][1]);
                    mma16816(acc[mt][2 * nt + 1], a[mt], b[nt][2], b[nt][3]);
                }
        }
    };

    // -------- pipeline: 3 stages --------
    if (NEXP == 1) { cpA(0); } else { ldgA(0); stsA(0); }
    cpB(0); CP_COMMIT();
    if (NCH > 1) {
        if (NEXP == 1) cpA(1); else ldgA(1);
        cpB(1);
    }
    CP_COMMIT();

#pragma unroll 1
    for (int ci = 0; ci < NCH; ci++) {
        CP_WAIT_1();
        __syncthreads();
        if (NEXP > 1 && ci + 1 < NCH) stsA(ci + 1);
        if (ci + 2 < NCH) {
            if (NEXP == 1) cpA(ci + 2); else ldgA(ci + 2);
            cpB(ci + 2);
        }
        CP_COMMIT();
        mmaStage(ci % 3);
    }

    // -------- epilogue --------
    float part[4][PEXP];
    if (EPI == 2) {
#pragma unroll
        for (int a = 0; a < 4; a++)
#pragma unroll
            for (int p = 0; p < PEXP; p++) part[a][p] = 0.0f;
    }
    const float2* gw2s2 = (const float2*)(smem + 4096);

#pragma unroll
    for (int mt = 0; mt < MT; mt++) {
#pragma unroll
        for (int h = 0; h < 2; h++) {
            const int r = wm * (MT * 16) + mt * 16 + tq + h * 8;
            float blv[PEXP];
            if (NEXP > 1) {
#pragma unroll
                for (int p = 0; p < PEXP; p++) blv[p] = blend_s[r * 8 + p];
            }
#pragma unroll
            for (int nn = 0; nn < 2 * NT; nn++) {
                const int col = wn * (NT * 16) + (nn >> 1) * 16 + (nn & 1) * 8 + tr * 2;
                float v0 = acc[mt][nn][h * 2 + 0];
                float v1 = acc[mt][nn][h * 2 + 1];
                if (NEXP == 1) {
                    v0 += bias_s[col]; v1 += bias_s[col + 1];
                } else {
                    float b0 = 0.0f, b1 = 0.0f;
#pragma unroll
                    for (int p = 0; p < PEXP; p++) {
                        b0 = fmaf(blv[p], bias_s[p * BN + col], b0);
                        b1 = fmaf(blv[p], bias_s[p * BN + col + 1], b1);
                    }
                    v0 += b0; v1 += b1;
                }
                if (EPI == 0) {
                    v0 = fmaxf(v0, 0.0f); v1 = fmaxf(v1, 0.0f);
                    __half2 hv = __floats2half2_rn(v0, v1);
                    *(uint32_t*)&Yh[(size_t)(row0 + r) * NTOT + n0 + col] = *(uint32_t*)&hv;
                } else if (EPI == 2) {
                    v0 = fmaxf(v0, 0.0f); v1 = fmaxf(v1, 0.0f);
                    const int a = mt * 2 + h;
#pragma unroll
                    for (int p = 0; p < PEXP; p++) {
                        const float2 g = gw2s2[p * 64 + (col >> 1)];
                        part[a][p] = fmaf(v0, g.x, fmaf(v1, g.y, part[a][p]));
                    }
                }
            }
        }
    }

    if (EPI == 2) {
#pragma unroll
        for (int a = 0; a < 4; a++)
#pragma unroll
            for (int p = 0; p < PEXP; p++) {
                part[a][p] += __shfl_xor_sync(0xffffffffu, part[a][p], 1);
                part[a][p] += __shfl_xor_sync(0xffffffffu, part[a][p], 2);
            }
        if (tr == 0) {
            const int j = blockIdx.x * 2 + wn;
#pragma unroll
            for (int a = 0; a < 4; a++) {
                const int grow = row0 + wm * (MT * 16) + (a >> 1) * 16 + (a & 1) * 8 + tq;
                float* dst = partOut + ((size_t)j * B_ + grow) * PEXP;
                *(float4*)dst       = make_float4(part[a][0], part[a][1], part[a][2], part[a][3]);
                *(float4*)(dst + 4) = make_float4(part[a][4], part[a][5], part[a][6], part[a][7]);
            }
        }
    }
}

// ======================= head GEMM (A resident in smem) ====================
// BM=64, BN=64, K=512, 8 experts. A tile (64x512 fp16 = 64KB) loaded ONCE;
// blend applied per-expert to A fragments in registers (hmul2 after ldsm).
// A-frag row map (m16n8k16): a0,a2 -> row tq ; a1,a3 -> row tq+8.
// smem PADDED past 114KB so only ONE CTA fits per SM -> 128 CTAs on 128 SMs.
__global__ __launch_bounds__(256, 1)
void head_gemm(const __half* __restrict__ A, const __half* __restrict__ W,
               const float* __restrict__ bias, const float* __restrict__ blend,
               float* __restrict__ Yf)
{
    constexpr int K = HIDD, BN = 64, NSTEP = PEXP * (K / 64);
    constexpr int OFF_A = 4096;            // bias 2KB + blend 2KB
    constexpr int OFF_B = OFF_A + 64 * 1024;

    extern __shared__ __align__(16) char smem[];
    float* bias_s  = (float*)smem;          // [8*64]
    float* blend_s = (float*)(smem + 2048); // [64*8]
    const uint32_t sb = smem_u32(smem);

    const int tid = threadIdx.x;
    const int wid = tid >> 5;
    const int t   = tid & 31;
    const int row0 = blockIdx.y * 64;

    for (int i = tid; i < PEXP * BN; i += 256) bias_s[i] = bias[i];
    for (int i = tid; i < 64 * 8; i += 256)
        blend_s[i] = blend[(size_t)(row0 + (i >> 3)) * PEXP + (i & 7)];
    __syncthreads();

    const int wm = wid >> 1, wn = wid & 1;
    const int aro = t & 15;
    const int akg = t >> 4;
    const int bno = ((t >> 4) << 3) + (t & 7);
    const int bkg = (t >> 3) & 1;
    const int tq  = t >> 2, tr = t & 3;

    // per-expert blend scalars for this thread's two A-frag rows
    uint32_t hbl[PEXP], hbh[PEXP];
    {
        const int r0 = wm * 16 + tq;
#pragma unroll
        for (int p = 0; p < PEXP; p++) {
            __half2 x = __half2half2(__float2half(blend_s[r0 * 8 + p]));
            __half2 y = __half2half2(__float2half(blend_s[(r0 + 8) * 8 + p]));
            hbl[p] = *(uint32_t*)&x;
            hbh[p] = *(uint32_t*)&y;
        }
    }

    float acc[4][4];
#pragma unroll
    for (int b = 0; b < 4; b++)
#pragma unroll
        for (int q = 0; q < 4; q++) acc[b][q] = 0.0f;

    // A: rows of 1024B; 128B sub-block per k-chunk, swizzle within sub-block
    auto cpA_all = [&]() {
#pragma unroll
        for (int it = 0; it < 16; it++) {
            const int idx = tid + it * 256;      // 4096 16B-chunks
            const int r = idx >> 6, c16 = idx & 63;
            const int c = c16 >> 3, ch8 = c16 & 7;
            const __half* src = A + (size_t)(row0 + r) * K + c16 * 8;
            CP_ASYNC16(sb + OFF_A + r * 1024 + c * 128 + ((ch8 ^ (r & 7)) << 4), src);
        }
    };
    auto cpB = [&](int ci) {
        const int p = ci & 7, kc64 = ci >> 3, s = ci % 3;
        const uint32_t stB = sb + OFF_B + (uint32_t)s * 8192;
#pragma unroll
        for (int it = 0; it < 2; it++) {
            const int idx = tid + it * 256;
            const int r = idx >> 3, ch = idx & 7;
            const __half* src = W + ((size_t)p * BN + r) * K + kc64 * 64 + ch * 8;
            CP_ASYNC16(stB + r * 128 + ((ch ^ (r & 7)) << 4), src);
        }
    };

    auto mmaStep = [&](int ci) {
        const int p = ci & 7, kc64 = ci >> 3, s = ci % 3;
        const uint32_t stA = sb + OFF_A;
        const uint32_t stB = sb + OFF_B + (uint32_t)s * 8192;
        const uint32_t h0 = hbl[p], h1 = hbh[p];
#pragma unroll
        for (int kc = 0; kc < 4; kc++) {
            uint32_t a[4], sa[4];
            const int row = wm * 16 + aro;
            const int ch = kc * 2 + akg;
            ldsm4(a, stA + row * 1024 + kc64 * 128 + ((ch ^ (row & 7)) << 4));
            // a0,a2 are row tq (h0); a1,a3 are row tq+8 (h1)
            sa[0] = hmul2u(a[0], h0);  sa[1] = hmul2u(a[1], h1);
            sa[2] = hmul2u(a[2], h0);  sa[3] = hmul2u(a[3], h1);
            uint32_t b[2][4];
#pragma unroll
            for (int nt = 0; nt < 2; nt++) {
                const int n = wn * 32 + nt * 16 + bno;
                const int chb = kc * 2 + bkg;
                ldsm4(b[nt], stB + n * 128 + ((chb ^ (n & 7)) << 4));
            }
            mma16816(acc[0], sa, b[0][0], b[0][1]);
            mma16816(acc[1], sa, b[0][2], b[0][3]);
            mma16816(acc[2], sa, b[1][0], b[1][1]);
            mma16816(acc[3], sa, b[1][2], b[1][3]);
        }
    };

    // pipeline: A + B0 in group 0; B1 in group 1; then 3-stage B ring
    cpA_all(); cpB(0); CP_COMMIT();
    cpB(1); CP_COMMIT();

#pragma unroll 1
    for (int ci = 0; ci < NSTEP; ci++) {
        CP_WAIT_1();
        __syncthreads();
        if (ci + 2 < NSTEP) cpB(ci + 2);
        CP_COMMIT();
        mmaStep(ci);
    }

    // -------- epilogue: blended bias + mu/std --------
#pragma unroll
    for (int h = 0; h < 2; h++) {
        const int r = wm * 16 + tq + h * 8;
        float blv[PEXP];
#pragma unroll
        for (int p = 0; p < PEXP; p++) blv[p] = blend_s[r * 8 + p];
#pragma unroll
        for (int nn = 0; nn < 4; nn++) {
            const int col = wn * 32 + (nn >> 1) * 16 + (nn & 1) * 8 + tr * 2;
            float v0 = acc[nn][h * 2 + 0];
            float v1 = acc[nn][h * 2 + 1];
            float b0 = 0.0f, b1 = 0.0f;
#pragma unroll
            for (int p = 0; p < PEXP; p++) {
                b0 = fmaf(blv[p], bias_s[p * BN + col], b0);
                b1 = fmaf(blv[p], bias_s[p * BN + col + 1], b1);
            }
            v0 += b0; v1 += b1;
            if (col >= 32)     v0 = expf(3.5f * tanhf(v0) - 1.5f);
            if (col + 1 >= 32) v1 = expf(3.5f * tanhf(v1) - 1.5f);
            *(float2*)&Yf[(size_t)(row0 + r) * BN + col] = make_float2(v0, v1);
        }
    }
}

// ======================= 8-partial sum + softmax ===========================
// 4 threads per row: each sums 2 of the 8 j-slices, 2 shfl combines, lane0 writes.
__global__ __launch_bounds__(256)
void softmax8(const float* __restrict__ part, const float* __restrict__ gb2,
              float* __restrict__ blend)
{
    const int gid  = blockIdx.x * 256 + threadIdx.x;   // 32768 threads
    const int row  = gid >> 2;
    const int quad = gid & 3;
    float l[PEXP];
#pragma unroll
    for (int p = 0; p < PEXP; p++) l[p] = 0.0f;
#pragma unroll
    for (int j = 0; j < 2; j++) {
        const int jj = quad * 2 + j;
        const float4* s = (const float4*)(part + ((size_t)jj * B_ + row) * PEXP);
        const float4 a = s[0], b = s[1];
        l[0] += a.x; l[1] += a.y; l[2] += a.z; l[3] += a.w;
        l[4] += b.x; l[5] += b.y; l[6] += b.z; l[7] += b.w;
    }
#pragma unroll
    for (int p = 0; p < PEXP; p++) {
        l[p] += __shfl_xor_sync(0xffffffffu, l[p], 1);
        l[p] += __shfl_xor_sync(0xffffffffu, l[p], 2);
    }

    float m = -1e30f;
#pragma unroll
    for (int p = 0; p < PEXP; p++) { l[p] += gb2[p]; m = fmaxf(m, l[p]); }
    float s = 0.0f;
#pragma unroll
    for (int p = 0; p < PEXP; p++) { l[p] = expf(l[p] - m); s += l[p]; }
    const float inv = 1.0f / s;
    if (quad == 0) {
        float4* dst = (float4*)(blend + (size_t)row * PEXP);
        dst[0] = make_float4(l[0] * inv, l[1] * inv, l[2] * inv, l[3] * inv);
        dst[1] = make_float4(l[4] * inv, l[5] * inv, l[6] * inv, l[7] * inv);
    }
}

// ======================= host launch =======================================
extern "C" void kernel_launch(void* const* d_in, const int* in_sizes, int n_in,
                              void* d_out, int out_size)
{
    const float* obs = (const float*)d_in[0];
    const float* gw0 = (const float*)d_in[1];
    const float* gb0 = (const float*)d_in[2];
    const float* gw1 = (const float*)d_in[3];
    const float* gb1 = (const float*)d_in[4];
    const float* gw2 = (const float*)d_in[5];
    const float* gb2 = (const float*)d_in[6];
    const float* ew0 = (const float*)d_in[7];
    const float* eb0 = (const float*)d_in[8];
    const float* ew1 = (const float*)d_in[9];
    const float* eb1 = (const float*)d_in[10];
    const float* ew2 = (const float*)d_in[11];
    const float* eb2 = (const float*)d_in[12];
    float* out = (float*)d_out;

    __half *obs16, *gw016, *gw116, *ew016, *ew116, *ew216;
    __half *act0, *actA, *actB;
    float *partb, *blend;
    cudaGetSymbolAddress((void**)&obs16, d_obs16);
    cudaGetSymbolAddress((void**)&gw016, d_gw016);
    cudaGetSymbolAddress((void**)&gw116, d_gw116);
    cudaGetSymbolAddress((void**)&ew016, d_ew016);
    cudaGetSymbolAddress((void**)&ew116, d_ew116);
    cudaGetSymbolAddress((void**)&ew216, d_ew216);
    cudaGetSymbolAddress((void**)&act0, d_act0);
    cudaGetSymbolAddress((void**)&actA, d_actA);
    cudaGetSymbolAddress((void**)&actB, d_actB);
    cudaGetSymbolAddress((void**)&partb, d_partbuf);
    cudaGetSymbolAddress((void**)&blend, d_blend);

    static const int S128  = 8192 + 3 * (128 * 128 + 128 * 128);   // 106496
    // head smem padded past 114KB so only ONE CTA fits per SM (128 CTAs -> 128 SMs)
    static const int SHEAD = 118784;
    cudaFuncSetAttribute(moe_gemm<1, 0, 128, 128, 256>, cudaFuncAttributeMaxDynamicSharedMemorySize, S128);
    cudaFuncSetAttribute(moe_gemm<1, 2, 128, 128, 512>, cudaFuncAttributeMaxDynamicSharedMemorySize, S128);
    cudaFuncSetAttribute(moe_gemm<8, 0, 128, 128, 256>, cudaFuncAttributeMaxDynamicSharedMemorySize, S128);
    cudaFuncSetAttribute(moe_gemm<8, 0, 128, 128, 512>, cudaFuncAttributeMaxDynamicSharedMemorySize, S128);
    cudaFuncSetAttribute(head_gemm, cudaFuncAttributeMaxDynamicSharedMemorySize, SHEAD);

    // -------- single batched convert --------
    CvtArgs ca;
    ca.src[0] = obs;  ca.dst[0] = obs16;
    ca.src[1] = gw0;  ca.dst[1] = gw016;
    ca.src[2] = gw1;  ca.dst[2] = gw116;
    ca.src[3] = ew0;  ca.dst[3] = ew016;
    ca.src[4] = ew1;  ca.dst[4] = ew116;
    ca.src[5] = ew2;  ca.dst[5] = ew216;
    int acc4 = 0;
    const int sizes4[6] = {B_ * OBSD / 4, HIDD * OBSD / 4, HIDD * HIDD / 4,
                           PEXP * HIDD * OBSD / 4, PEXP * HIDD * HIDD / 4,
                           PEXP * 2 * ACTD * HIDD / 4};
    for (int k = 0; k < 6; k++) { acc4 += sizes4[k]; ca.end[k] = acc4; }
    cvt_all<<<1024, 256>>>(ca, acc4);

    const dim3 blk(256);
    const dim3 g512(HIDD / 128, B_ / 128);   // (4, 64)
    // gate trunk; g1 fuses the gate-head logits into its epilogue
    moe_gemm<1, 0, 128, 128, 256><<<g512, blk, S128>>>(obs16, gw016, gb0, nullptr,
                                                       nullptr, nullptr, act0, nullptr, HIDD);
    moe_gemm<1, 2, 128, 128, 512><<<g512, blk, S128>>>(act0, gw116, gb1, nullptr,
                                                       gw2, partb, nullptr, nullptr, HIDD);
    softmax8<<<B_ * 4 / 256, blk>>>(partb, gb2, blend);
    // blended experts (blend folded into A operand)
    moe_gemm<8, 0, 128, 128, 256><<<g512, blk, S128>>>(obs16, ew016, eb0, blend,
                                                       nullptr, nullptr, actA, nullptr, HIDD);
    moe_gemm<8, 0, 128, 128, 512><<<g512, blk, S128>>>(actA, ew116, eb1, blend,
                                                       nullptr, nullptr, actB, nullptr, HIDD);
    // head: A-resident smem kernel, 128 CTAs on 128 distinct SMs (occ 1 via smem pad)
    head_gemm<<<dim3(1, B_ / 64), blk, SHEAD>>>(actB, ew216, eb2, blend, out);
}

// round 15
// speedup vs baseline: 1.0041x; 1.0041x over previous
#include <cuda_runtime.h>
#include <cuda_fp16.h>
#include <cstdint>
#include <math.h>

#define B_    8192
#define OBSD  256
#define ACTD  32
#define HIDD  512
#define PEXP  8

// ======================= scratch (no allocs allowed) =======================
__device__ __align__(16) __half d_obs16[B_ * OBSD];
__device__ __align__(16) __half d_gw016[HIDD * OBSD];
__device__ __align__(16) __half d_gw116[HIDD * HIDD];
__device__ __align__(16) __half d_ew016[PEXP * HIDD * OBSD];
__device__ __align__(16) __half d_ew116[PEXP * HIDD * HIDD];
__device__ __align__(16) __half d_ew216[PEXP * 2 * ACTD * HIDD];
__device__ __align__(16) __half d_act0[B_ * HIDD];
__device__ __align__(16) __half d_actA[B_ * HIDD];
__device__ __align__(16) __half d_actB[B_ * HIDD];
__device__ __align__(16) float d_partbuf[8 * B_ * PEXP];
__device__ __align__(16) float d_blend[B_ * PEXP];

// ======================= low-level helpers =================================
__device__ __forceinline__ uint32_t smem_u32(const void* p) {
    uint32_t a;
    asm("{ .reg .u64 t; cvta.to.shared.u64 t, %1; cvt.u32.u64 %0, t; }" : "=r"(a) : "l"(p));
    return a;
}
#define CP_ASYNC16(dst, src) \
    asm volatile("cp.async.cg.shared.global [%0], [%1], 16;" :: "r"(dst), "l"(src))
#define CP_COMMIT() asm volatile("cp.async.commit_group;" ::: "memory")
#define CP_WAIT_1() asm volatile("cp.async.wait_group 1;" ::: "memory")

__device__ __forceinline__ void ldsm4(uint32_t* r, uint32_t addr) {
    asm volatile("ldmatrix.sync.aligned.m8n8.x4.shared.b16 {%0,%1,%2,%3}, [%4];"
                 : "=r"(r[0]), "=r"(r[1]), "=r"(r[2]), "=r"(r[3]) : "r"(addr));
}
__device__ __forceinline__ void mma16816(float* c, const uint32_t* a, uint32_t b0, uint32_t b1) {
    asm volatile(
        "mma.sync.aligned.m16n8k16.row.col.f32.f16.f16.f32 "
        "{%0,%1,%2,%3}, {%4,%5,%6,%7}, {%8,%9}, {%0,%1,%2,%3};"
        : "+f"(c[0]), "+f"(c[1]), "+f"(c[2]), "+f"(c[3])
        : "r"(a[0]), "r"(a[1]), "r"(a[2]), "r"(a[3]), "r"(b0), "r"(b1));
}
__device__ __forceinline__ uint32_t hmul2u(uint32_t a, uint32_t b) {
    uint32_t r;
    asm("mul.rn.f16x2 %0, %1, %2;" : "=r"(r) : "r"(a), "r"(b));
    return r;
}

// ======================= batched fp32 -> fp16 convert ======================
struct CvtArgs {
    const float* src[6];
    __half*      dst[6];
    int          end[6];   // prefix-sum ends, in float4 units
};

__global__ __launch_bounds__(256)
void cvt_all(CvtArgs a, int total4) {
    int i = blockIdx.x * blockDim.x + threadIdx.x;
    const int stride = gridDim.x * blockDim.x;
    for (; i < total4; i += stride) {
        int seg = 0;
#pragma unroll
        for (int k = 0; k < 5; k++) seg += (i >= a.end[k]) ? 1 : 0;
        const int base = (seg == 0) ? 0 : a.end[seg - 1];
        const int off = i - base;
        const float4 v = *(const float4*)(a.src[seg] + (size_t)off * 4);
        __half2 h0 = __floats2half2_rn(v.x, v.y);
        __half2 h1 = __floats2half2_rn(v.z, v.w);
        *(uint2*)(a.dst[seg] + (size_t)off * 4) = make_uint2(*(uint32_t*)&h0, *(uint32_t*)&h1);
    }
}

// ======================= fp16 blended MoE GEMM =============================
// EPI 0: relu -> fp16 store.  EPI 2: relu, NO Y store; gate-logit partials.
template <int NEXP, int EPI, int BM, int BN, int K>
__global__ __launch_bounds__(256, 2)
void moe_gemm(const __half* __restrict__ A, const __half* __restrict__ W,
              const float* __restrict__ bias, const float* __restrict__ blend,
              const float* __restrict__ gw2, float* __restrict__ partOut,
              __half* __restrict__ Yh, float* __restrict__ Yf, int NTOT)
{
    constexpr int NCK   = K / 64;
    constexpr int NCH   = NEXP * NCK;
    constexpr int MT    = BM / 64;
    constexpr int NT    = BN / 32;
    constexpr int AIT   = BM / 32;
    constexpr int BIT_  = BN / 32;
    constexpr int STAGE = BM * 128 + BN * 128;

    extern __shared__ __align__(16) char smem[];
    float* bias_s  = (float*)smem;           // [NEXP*BN]
    float* blend_s = (float*)(smem + 4096);  // [BM*8]  (EPI2: gw2 slice [8][128])
    const uint32_t sb = smem_u32(smem);

    const int tid = threadIdx.x;
    const int wid = tid >> 5;
    const int t   = tid & 31;
    const int row0 = blockIdx.y * BM;
    const int n0   = blockIdx.x * BN;

    for (int i = tid; i < NEXP * BN; i += 256)
        bias_s[i] = bias[(size_t)(i / BN) * NTOT + n0 + (i % BN)];
    if (NEXP > 1)
        for (int i = tid; i < BM * 8; i += 256)
            blend_s[i] = blend[(size_t)(row0 + (i >> 3)) * PEXP + (i & 7)];
    if (EPI == 2)
        for (int i = tid; i < PEXP * BN; i += 256)
            blend_s[i] = gw2[(size_t)(i >> 7) * HIDD + n0 + (i & 127)];
    __syncthreads();

    const int wm = wid >> 1, wn = wid & 1;
    const int aro = t & 15;
    const int akg = t >> 4;
    const int bno = ((t >> 4) << 3) + (t & 7);
    const int bkg = (t >> 3) & 1;
    const int tq  = t >> 2, tr = t & 3;

    float acc[MT][2 * NT][4];
#pragma unroll
    for (int a = 0; a < MT; a++)
#pragma unroll
        for (int b = 0; b < 2 * NT; b++)
#pragma unroll
            for (int q = 0; q < 4; q++) acc[a][b][q] = 0.0f;

    uint4 areg[AIT];

    auto ldgA = [&](int ci) {
        const int kk = (ci % NCK) * 64;
#pragma unroll
        for (int it = 0; it < AIT; it++) {
            const int idx = tid + it * 256;
            const int r = idx >> 3, ch = idx & 7;
            areg[it] = *(const uint4*)(A + (size_t)(row0 + r) * K + kk + ch * 8);
        }
    };
    auto stsA = [&](int ci) {
        const int p = ci / NCK;
        const int s = ci % 3;
        const uint32_t off0 = 8192 + (uint32_t)s * STAGE;
#pragma unroll
        for (int it = 0; it < AIT; it++) {
            const int idx = tid + it * 256;
            const int r = idx >> 3, ch = idx & 7;
            uint4 v = areg[it];
            const __half hb = __float2half(blend_s[r * 8 + p]);
            __half2 hb2 = __half2half2(hb);
            const uint32_t b2 = *(uint32_t*)&hb2;
            v.x = hmul2u(v.x, b2);  v.y = hmul2u(v.y, b2);
            v.z = hmul2u(v.z, b2);  v.w = hmul2u(v.w, b2);
            *(uint4*)(smem + off0 + r * 128 + ((ch ^ (r & 7)) << 4)) = v;
        }
    };
    auto cpA = [&](int ci) {
        const int kk = (ci % NCK) * 64;
        const int s  = ci % 3;
        const uint32_t stA = sb + 8192 + (uint32_t)s * STAGE;
#pragma unroll
        for (int it = 0; it < AIT; it++) {
            const int idx = tid + it * 256;
            const int r = idx >> 3, ch = idx & 7;
            const __half* src = A + (size_t)(row0 + r) * K + kk + ch * 8;
            CP_ASYNC16(stA + r * 128 + ((ch ^ (r & 7)) << 4), src);
        }
    };
    auto cpB = [&](int ci) {
        const int p  = ci / NCK;
        const int kk = (ci % NCK) * 64;
        const int s  = ci % 3;
        const uint32_t stB = sb + 8192 + (uint32_t)s * STAGE + BM * 128;
#pragma unroll
        for (int it = 0; it < BIT_; it++) {
            const int idx = tid + it * 256;
            const int r = idx >> 3, ch = idx & 7;
            const __half* src = W + ((size_t)p * NTOT + n0 + r) * K + kk + ch * 8;
            CP_ASYNC16(stB + r * 128 + ((ch ^ (r & 7)) << 4), src);
        }
    };

    auto mmaStage = [&](int s) {
        const uint32_t stA = sb + 8192 + (uint32_t)s * STAGE;
        const uint32_t stB = stA + BM * 128;
#pragma unroll
        for (int kc = 0; kc < 4; kc++) {
            uint32_t a[MT][4];
#pragma unroll
            for (int mt = 0; mt < MT; mt++) {
                const int row = wm * (MT * 16) + mt * 16 + aro;
                const int ch = kc * 2 + akg;
                ldsm4(a[mt], stA + row * 128 + ((ch ^ (row & 7)) << 4));
            }
            uint32_t b[NT][4];
#pragma unroll
            for (int nt = 0; nt < NT; nt++) {
                const int n = wn * (NT * 16) + nt * 16 + bno;
                const int ch = kc * 2 + bkg;
                ldsm4(b[nt], stB + n * 128 + ((ch ^ (n & 7)) << 4));
            }
#pragma unroll
            for (int mt = 0; mt < MT; mt++)
#pragma unroll
                for (int nt = 0; nt < NT; nt++) {
                    mma16816(acc[mt][2 * nt + 0], a[mt], b[nt][0], b[nt][1]);
                    mma16816(acc[mt][2 * nt + 1], a[mt], b[nt][2], b[nt][3]);
                }
        }
    };

    // -------- pipeline: 3 stages --------
    if (NEXP == 1) { cpA(0); } else { ldgA(0); stsA(0); }
    cpB(0); CP_COMMIT();
    if (NCH > 1) {
        if (NEXP == 1) cpA(1); else ldgA(1);
        cpB(1);
    }
    CP_COMMIT();

#pragma unroll 1
    for (int ci = 0; ci < NCH; ci++) {
        CP_WAIT_1();
        __syncthreads();
        if (NEXP > 1 && ci + 1 < NCH) stsA(ci + 1);
        if (ci + 2 < NCH) {
            if (NEXP == 1) cpA(ci + 2); else ldgA(ci + 2);
            cpB(ci + 2);
        }
        CP_COMMIT();
        mmaStage(ci % 3);
    }

    // -------- epilogue --------
    float part[4][PEXP];
    if (EPI == 2) {
#pragma unroll
        for (int a = 0; a < 4; a++)
#pragma unroll
            for (int p = 0; p < PEXP; p++) part[a][p] = 0.0f;
    }
    const float2* gw2s2 = (const float2*)(smem + 4096);

#pragma unroll
    for (int mt = 0; mt < MT; mt++) {
#pragma unroll
        for (int h = 0; h < 2; h++) {
            const int r = wm * (MT * 16) + mt * 16 + tq + h * 8;
            float blv[PEXP];
            if (NEXP > 1) {
#pragma unroll
                for (int p = 0; p < PEXP; p++) blv[p] = blend_s[r * 8 + p];
            }
#pragma unroll
            for (int nn = 0; nn < 2 * NT; nn++) {
                const int col = wn * (NT * 16) + (nn >> 1) * 16 + (nn & 1) * 8 + tr * 2;
                float v0 = acc[mt][nn][h * 2 + 0];
                float v1 = acc[mt][nn][h * 2 + 1];
                if (NEXP == 1) {
                    v0 += bias_s[col]; v1 += bias_s[col + 1];
                } else {
                    float b0 = 0.0f, b1 = 0.0f;
#pragma unroll
                    for (int p = 0; p < PEXP; p++) {
                        b0 = fmaf(blv[p], bias_s[p * BN + col], b0);
                        b1 = fmaf(blv[p], bias_s[p * BN + col + 1], b1);
                    }
                    v0 += b0; v1 += b1;
                }
                if (EPI == 0) {
                    v0 = fmaxf(v0, 0.0f); v1 = fmaxf(v1, 0.0f);
                    __half2 hv = __floats2half2_rn(v0, v1);
                    *(uint32_t*)&Yh[(size_t)(row0 + r) * NTOT + n0 + col] = *(uint32_t*)&hv;
                } else if (EPI == 2) {
                    v0 = fmaxf(v0, 0.0f); v1 = fmaxf(v1, 0.0f);
                    const int a = mt * 2 + h;
#pragma unroll
                    for (int p = 0; p < PEXP; p++) {
                        const float2 g = gw2s2[p * 64 + (col >> 1)];
                        part[a][p] = fmaf(v0, g.x, fmaf(v1, g.y, part[a][p]));
                    }
                }
            }
        }
    }

    if (EPI == 2) {
#pragma unroll
        for (int a = 0; a < 4; a++)
#pragma unroll
            for (int p = 0; p < PEXP; p++) {
                part[a][p] += __shfl_xor_sync(0xffffffffu, part[a][p], 1);
                part[a][p] += __shfl_xor_sync(0xffffffffu, part[a][p], 2);
            }
        if (tr == 0) {
            const int j = blockIdx.x * 2 + wn;
#pragma unroll
            for (int a = 0; a < 4; a++) {
                const int grow = row0 + wm * (MT * 16) + (a >> 1) * 16 + (a & 1) * 8 + tq;
                float* dst = partOut + ((size_t)j * B_ + grow) * PEXP;
                *(float4*)dst       = make_float4(part[a][0], part[a][1], part[a][2], part[a][3]);
                *(float4*)(dst + 4) = make_float4(part[a][4], part[a][5], part[a][6], part[a][7]);
            }
        }
    }
}

// ======================= head GEMM (A resident in smem) ====================
// BM=64, BN=64, K=512, 8 experts. A tile (64x512 fp16 = 64KB) loaded ONCE;
// blend applied per-expert to A fragments in registers (hmul2 after ldsm).
// A-frag row map (m16n8k16): a0,a2 -> row tq ; a1,a3 -> row tq+8.
// smem PADDED past 114KB so only ONE CTA fits per SM -> 128 CTAs on 128 SMs.
__global__ __launch_bounds__(256, 1)
void head_gemm(const __half* __restrict__ A, const __half* __restrict__ W,
               const float* __restrict__ bias, const float* __restrict__ blend,
               float* __restrict__ Yf)
{
    constexpr int K = HIDD, BN = 64, NSTEP = PEXP * (K / 64);
    constexpr int OFF_A = 4096;            // bias 2KB + blend 2KB
    constexpr int OFF_B = OFF_A + 64 * 1024;

    extern __shared__ __align__(16) char smem[];
    float* bias_s  = (float*)smem;          // [8*64]
    float* blend_s = (float*)(smem + 2048); // [64*8]
    const uint32_t sb = smem_u32(smem);

    const int tid = threadIdx.x;
    const int wid = tid >> 5;
    const int t   = tid & 31;
    const int row0 = blockIdx.y * 64;

    for (int i = tid; i < PEXP * BN; i += 256) bias_s[i] = bias[i];
    for (int i = tid; i < 64 * 8; i += 256)
        blend_s[i] = blend[(size_t)(row0 + (i >> 3)) * PEXP + (i & 7)];
    __syncthreads();

    const int wm = wid >> 1, wn = wid & 1;
    const int aro = t & 15;
    const int akg = t >> 4;
    const int bno = ((t >> 4) << 3) + (t & 7);
    const int bkg = (t >> 3) & 1;
    const int tq  = t >> 2, tr = t & 3;

    // per-expert blend scalars for this thread's two A-frag rows
    uint32_t hbl[PEXP], hbh[PEXP];
    {
        const int r0 = wm * 16 + tq;
#pragma unroll
        for (int p = 0; p < PEXP; p++) {
            __half2 x = __half2half2(__float2half(blend_s[r0 * 8 + p]));
            __half2 y = __half2half2(__float2half(blend_s[(r0 + 8) * 8 + p]));
            hbl[p] = *(uint32_t*)&x;
            hbh[p] = *(uint32_t*)&y;
        }
    }

    float acc[4][4];
#pragma unroll
    for (int b = 0; b < 4; b++)
#pragma unroll
        for (int q = 0; q < 4; q++) acc[b][q] = 0.0f;

    // A: rows of 1024B; 128B sub-block per k-chunk, swizzle within sub-block
    auto cpA_all = [&]() {
#pragma unroll
        for (int it = 0; it < 16; it++) {
            const int idx = tid + it * 256;      // 4096 16B-chunks
            const int r = idx >> 6, c16 = idx & 63;
            const int c = c16 >> 3, ch8 = c16 & 7;
            const __half* src = A + (size_t)(row0 + r) * K + c16 * 8;
            CP_ASYNC16(sb + OFF_A + r * 1024 + c * 128 + ((ch8 ^ (r & 7)) << 4), src);
        }
    };
    auto cpB = [&](int ci) {
        const int p = ci & 7, kc64 = ci >> 3, s = ci % 3;
        const uint32_t stB = sb + OFF_B + (uint32_t)s * 8192;
#pragma unroll
        for (int it = 0; it < 2; it++) {
            const int idx = tid + it * 256;
            const int r = idx >> 3, ch = idx & 7;
            const __half* src = W + ((size_t)p * BN + r) * K + kc64 * 64 + ch * 8;
            CP_ASYNC16(stB + r * 128 + ((ch ^ (r & 7)) << 4), src);
        }
    };

    auto mmaStep = [&](int ci) {
        const int p = ci & 7, kc64 = ci >> 3, s = ci % 3;
        const uint32_t stA = sb + OFF_A;
        const uint32_t stB = sb + OFF_B + (uint32_t)s * 8192;
        const uint32_t h0 = hbl[p], h1 = hbh[p];
#pragma unroll
        for (int kc = 0; kc < 4; kc++) {
            uint32_t a[4], sa[4];
            const int row = wm * 16 + aro;
            const int ch = kc * 2 + akg;
            ldsm4(a, stA + row * 1024 + kc64 * 128 + ((ch ^ (row & 7)) << 4));
            // a0,a2 are row tq (h0); a1,a3 are row tq+8 (h1)
            sa[0] = hmul2u(a[0], h0);  sa[1] = hmul2u(a[1], h1);
            sa[2] = hmul2u(a[2], h0);  sa[3] = hmul2u(a[3], h1);
            uint32_t b[2][4];
#pragma unroll
            for (int nt = 0; nt < 2; nt++) {
                const int n = wn * 32 + nt * 16 + bno;
                const int chb = kc * 2 + bkg;
                ldsm4(b[nt], stB + n * 128 + ((chb ^ (n & 7)) << 4));
            }
            mma16816(acc[0], sa, b[0][0], b[0][1]);
            mma16816(acc[1], sa, b[0][2], b[0][3]);
            mma16816(acc[2], sa, b[1][0], b[1][1]);
            mma16816(acc[3], sa, b[1][2], b[1][3]);
        }
    };

    // pipeline: A + B0 in group 0; B1 in group 1; then 3-stage B ring
    cpA_all(); cpB(0); CP_COMMIT();
    cpB(1); CP_COMMIT();

#pragma unroll 1
    for (int ci = 0; ci < NSTEP; ci++) {
        CP_WAIT_1();
        __syncthreads();
        if (ci + 2 < NSTEP) cpB(ci + 2);
        CP_COMMIT();
        mmaStep(ci);
    }

    // -------- epilogue: blended bias + mu/std --------
#pragma unroll
    for (int h = 0; h < 2; h++) {
        const int r = wm * 16 + tq + h * 8;
        float blv[PEXP];
#pragma unroll
        for (int p = 0; p < PEXP; p++) blv[p] = blend_s[r * 8 + p];
#pragma unroll
        for (int nn = 0; nn < 4; nn++) {
            const int col = wn * 32 + (nn >> 1) * 16 + (nn & 1) * 8 + tr * 2;
            float v0 = acc[nn][h * 2 + 0];
            float v1 = acc[nn][h * 2 + 1];
            float b0 = 0.0f, b1 = 0.0f;
#pragma unroll
            for (int p = 0; p < PEXP; p++) {
                b0 = fmaf(blv[p], bias_s[p * BN + col], b0);
                b1 = fmaf(blv[p], bias_s[p * BN + col + 1], b1);
            }
            v0 += b0; v1 += b1;
            if (col >= 32)     v0 = expf(3.5f * tanhf(v0) - 1.5f);
            if (col + 1 >= 32) v1 = expf(3.5f * tanhf(v1) - 1.5f);
            *(float2*)&Yf[(size_t)(row0 + r) * BN + col] = make_float2(v0, v1);
        }
    }
}

// ======================= 8-partial sum + softmax ===========================
// 4 threads per row: each sums 2 of the 8 j-slices, 2 shfl combines, lane0 writes.
__global__ __launch_bounds__(256)
void softmax8(const float* __restrict__ part, const float* __restrict__ gb2,
              float* __restrict__ blend)
{
    const int gid  = blockIdx.x * 256 + threadIdx.x;   // 32768 threads
    const int row  = gid >> 2;
    const int quad = gid & 3;
    float l[PEXP];
#pragma unroll
    for (int p = 0; p < PEXP; p++) l[p] = 0.0f;
#pragma unroll
    for (int j = 0; j < 2; j++) {
        const int jj = quad * 2 + j;
        const float4* s = (const float4*)(part + ((size_t)jj * B_ + row) * PEXP);
        const float4 a = s[0], b = s[1];
        l[0] += a.x; l[1] += a.y; l[2] += a.z; l[3] += a.w;
        l[4] += b.x; l[5] += b.y; l[6] += b.z; l[7] += b.w;
    }
#pragma unroll
    for (int p = 0; p < PEXP; p++) {
        l[p] += __shfl_xor_sync(0xffffffffu, l[p], 1);
        l[p] += __shfl_xor_sync(0xffffffffu, l[p], 2);
    }

    float m = -1e30f;
#pragma unroll
    for (int p = 0; p < PEXP; p++) { l[p] += gb2[p]; m = fmaxf(m, l[p]); }
    float s = 0.0f;
#pragma unroll
    for (int p = 0; p < PEXP; p++) { l[p] = expf(l[p] - m); s += l[p]; }
    const float inv = 1.0f / s;
    if (quad == 0) {
        float4* dst = (float4*)(blend + (size_t)row * PEXP);
        dst[0] = make_float4(l[0] * inv, l[1] * inv, l[2] * inv, l[3] * inv);
        dst[1] = make_float4(l[4] * inv, l[5] * inv, l[6] * inv, l[7] * inv);
    }
}

// ======================= host launch =======================================
extern "C" void kernel_launch(void* const* d_in, const int* in_sizes, int n_in,
                              void* d_out, int out_size)
{
    const float* obs = (const float*)d_in[0];
    const float* gw0 = (const float*)d_in[1];
    const float* gb0 = (const float*)d_in[2];
    const float* gw1 = (const float*)d_in[3];
    const float* gb1 = (const float*)d_in[4];
    const float* gw2 = (const float*)d_in[5];
    const float* gb2 = (const float*)d_in[6];
    const float* ew0 = (const float*)d_in[7];
    const float* eb0 = (const float*)d_in[8];
    const float* ew1 = (const float*)d_in[9];
    const float* eb1 = (const float*)d_in[10];
    const float* ew2 = (const float*)d_in[11];
    const float* eb2 = (const float*)d_in[12];
    float* out = (float*)d_out;

    __half *obs16, *gw016, *gw116, *ew016, *ew116, *ew216;
    __half *act0, *actA, *actB;
    float *partb, *blend;
    cudaGetSymbolAddress((void**)&obs16, d_obs16);
    cudaGetSymbolAddress((void**)&gw016, d_gw016);
    cudaGetSymbolAddress((void**)&gw116, d_gw116);
    cudaGetSymbolAddress((void**)&ew016, d_ew016);
    cudaGetSymbolAddress((void**)&ew116, d_ew116);
    cudaGetSymbolAddress((void**)&ew216, d_ew216);
    cudaGetSymbolAddress((void**)&act0, d_act0);
    cudaGetSymbolAddress((void**)&actA, d_actA);
    cudaGetSymbolAddress((void**)&actB, d_actB);
    cudaGetSymbolAddress((void**)&partb, d_partbuf);
    cudaGetSymbolAddress((void**)&blend, d_blend);

    static const int S128  = 8192 + 3 * (128 * 128 + 128 * 128);   // 106496
    // head smem padded past 114KB so only ONE CTA fits per SM (128 CTAs -> 128 SMs)
    static const int SHEAD = 118784;
    cudaFuncSetAttribute(moe_gemm<1, 0, 128, 128, 256>, cudaFuncAttributeMaxDynamicSharedMemorySize, S128);
    cudaFuncSetAttribute(moe_gemm<1, 2, 128, 128, 512>, cudaFuncAttributeMaxDynamicSharedMemorySize, S128);
    cudaFuncSetAttribute(moe_gemm<8, 0, 128, 128, 256>, cudaFuncAttributeMaxDynamicSharedMemorySize, S128);
    cudaFuncSetAttribute(moe_gemm<8, 0, 128, 128, 512>, cudaFuncAttributeMaxDynamicSharedMemorySize, S128);
    cudaFuncSetAttribute(head_gemm, cudaFuncAttributeMaxDynamicSharedMemorySize, SHEAD);

    // -------- single batched convert --------
    CvtArgs ca;
    ca.src[0] = obs;  ca.dst[0] = obs16;
    ca.src[1] = gw0;  ca.dst[1] = gw016;
    ca.src[2] = gw1;  ca.dst[2] = gw116;
    ca.src[3] = ew0;  ca.dst[3] = ew016;
    ca.src[4] = ew1;  ca.dst[4] = ew116;
    ca.src[5] = ew2;  ca.dst[5] = ew216;
    int acc4 = 0;
    const int sizes4[6] = {B_ * OBSD / 4, HIDD * OBSD / 4, HIDD * HIDD / 4,
                           PEXP * HIDD * OBSD / 4, PEXP * HIDD * HIDD / 4,
                           PEXP * 2 * ACTD * HIDD / 4};
    for (int k = 0; k < 6; k++) { acc4 += sizes4[k]; ca.end[k] = acc4; }
    cvt_all<<<1024, 256>>>(ca, acc4);

    const dim3 blk(256);
    const dim3 g512(HIDD / 128, B_ / 128);   // (4, 64)
    // gate trunk; g1 fuses the gate-head logits into its epilogue
    moe_gemm<1, 0, 128, 128, 256><<<g512, blk, S128>>>(obs16, gw016, gb0, nullptr,
                                                       nullptr, nullptr, act0, nullptr, HIDD);
    moe_gemm<1, 2, 128, 128, 512><<<g512, blk, S128>>>(act0, gw116, gb1, nullptr,
                                                       gw2, partb, nullptr, nullptr, HIDD);
    softmax8<<<B_ * 4 / 256, blk>>>(partb, gb2, blend);
    // blended experts (blend folded into A operand)
    moe_gemm<8, 0, 128, 128, 256><<<g512, blk, S128>>>(obs16, ew016, eb0, blend,
                                                       nullptr, nullptr, actA, nullptr, HIDD);
    moe_gemm<8, 0, 128, 128, 512><<<g512, blk, S128>>>(actA, ew116, eb1, blend,
                                                       nullptr, nullptr, actB, nullptr, HIDD);
    // head: A-resident smem kernel, 128 CTAs on 128 distinct SMs (occ 1 via smem pad)
    head_gemm<<<dim3(1, B_ / 64), blk, SHEAD>>>(actB, ew216, eb2, blend, out);
}

// round 16
// speedup vs baseline: 1.0077x; 1.0037x over previous
#include <cuda_runtime.h>
#include <cuda_fp16.h>
#include <cstdint>
#include <math.h>

#define B_    8192
#define OBSD  256
#define ACTD  32
#define HIDD  512
#define PEXP  8

// ======================= scratch (no allocs allowed) =======================
__device__ __align__(16) __half d_obs16[B_ * OBSD];
__device__ __align__(16) __half d_gw016[HIDD * OBSD];
__device__ __align__(16) __half d_gw116[HIDD * HIDD];
__device__ __align__(16) __half d_ew016[PEXP * HIDD * OBSD];
__device__ __align__(16) __half d_ew116[PEXP * HIDD * HIDD];
__device__ __align__(16) __half d_ew216[PEXP * 2 * ACTD * HIDD];
__device__ __align__(16) __half d_act0[B_ * HIDD];
__device__ __align__(16) __half d_actA[B_ * HIDD];
__device__ __align__(16) __half d_actB[B_ * HIDD];
__device__ __align__(16) float d_partbuf[8 * B_ * PEXP];
__device__ __align__(16) float d_blend[B_ * PEXP];

// ======================= low-level helpers =================================
__device__ __forceinline__ uint32_t smem_u32(const void* p) {
    uint32_t a;
    asm("{ .reg .u64 t; cvta.to.shared.u64 t, %1; cvt.u32.u64 %0, t; }" : "=r"(a) : "l"(p));
    return a;
}
#define CP_ASYNC16(dst, src) \
    asm volatile("cp.async.cg.shared.global [%0], [%1], 16;" :: "r"(dst), "l"(src))
#define CP_COMMIT() asm volatile("cp.async.commit_group;" ::: "memory")
#define CP_WAIT_1() asm volatile("cp.async.wait_group 1;" ::: "memory")

__device__ __forceinline__ void ldsm4(uint32_t* r, uint32_t addr) {
    asm volatile("ldmatrix.sync.aligned.m8n8.x4.shared.b16 {%0,%1,%2,%3}, [%4];"
                 : "=r"(r[0]), "=r"(r[1]), "=r"(r[2]), "=r"(r[3]) : "r"(addr));
}
__device__ __forceinline__ void mma16816(float* c, const uint32_t* a, uint32_t b0, uint32_t b1) {
    asm volatile(
        "mma.sync.aligned.m16n8k16.row.col.f32.f16.f16.f32 "
        "{%0,%1,%2,%3}, {%4,%5,%6,%7}, {%8,%9}, {%0,%1,%2,%3};"
        : "+f"(c[0]), "+f"(c[1]), "+f"(c[2]), "+f"(c[3])
        : "r"(a[0]), "r"(a[1]), "r"(a[2]), "r"(a[3]), "r"(b0), "r"(b1));
}
__device__ __forceinline__ uint32_t hmul2u(uint32_t a, uint32_t b) {
    uint32_t r;
    asm("mul.rn.f16x2 %0, %1, %2;" : "=r"(r) : "r"(a), "r"(b));
    return r;
}

// ======================= batched fp32 -> fp16 convert ======================
struct CvtArgs {
    const float* src[6];
    __half*      dst[6];
    int          end[6];   // prefix-sum ends, in float4 units
};

__global__ __launch_bounds__(256)
void cvt_all(CvtArgs a, int total4) {
    int i = blockIdx.x * blockDim.x + threadIdx.x;
    const int stride = gridDim.x * blockDim.x;
    for (; i < total4; i += stride) {
        int seg = 0;
#pragma unroll
        for (int k = 0; k < 5; k++) seg += (i >= a.end[k]) ? 1 : 0;
        const int base = (seg == 0) ? 0 : a.end[seg - 1];
        const int off = i - base;
        const float4 v = *(const float4*)(a.src[seg] + (size_t)off * 4);
        __half2 h0 = __floats2half2_rn(v.x, v.y);
        __half2 h1 = __floats2half2_rn(v.z, v.w);
        *(uint2*)(a.dst[seg] + (size_t)off * 4) = make_uint2(*(uint32_t*)&h0, *(uint32_t*)&h1);
    }
}

// ======================= fp16 blended MoE GEMM =============================
// EPI 0: relu -> fp16 store.  EPI 2: relu, NO Y store; gate-logit partials.
template <int NEXP, int EPI, int BM, int BN, int K>
__global__ __launch_bounds__(256, 2)
void moe_gemm(const __half* __restrict__ A, const __half* __restrict__ W,
              const float* __restrict__ bias, const float* __restrict__ blend,
              const float* __restrict__ gw2, float* __restrict__ partOut,
              __half* __restrict__ Yh, float* __restrict__ Yf, int NTOT)
{
    constexpr int NCK   = K / 64;
    constexpr int NCH   = NEXP * NCK;
    constexpr int MT    = BM / 64;
    constexpr int NT    = BN / 32;
    constexpr int AIT   = BM / 32;
    constexpr int BIT_  = BN / 32;
    constexpr int STAGE = BM * 128 + BN * 128;

    extern __shared__ __align__(16) char smem[];
    float* bias_s  = (float*)smem;           // [NEXP*BN]
    float* blend_s = (float*)(smem + 4096);  // [BM*8]  (EPI2: gw2 slice [8][128])
    const uint32_t sb = smem_u32(smem);

    const int tid = threadIdx.x;
    const int wid = tid >> 5;
    const int t   = tid & 31;
    const int row0 = blockIdx.y * BM;
    const int n0   = blockIdx.x * BN;

    for (int i = tid; i < NEXP * BN; i += 256)
        bias_s[i] = bias[(size_t)(i / BN) * NTOT + n0 + (i % BN)];
    if (NEXP > 1)
        for (int i = tid; i < BM * 8; i += 256)
            blend_s[i] = blend[(size_t)(row0 + (i >> 3)) * PEXP + (i & 7)];
    if (EPI == 2)
        for (int i = tid; i < PEXP * BN; i += 256)
            blend_s[i] = gw2[(size_t)(i >> 7) * HIDD + n0 + (i & 127)];
    __syncthreads();

    const int wm = wid >> 1, wn = wid & 1;
    const int aro = t & 15;
    const int akg = t >> 4;
    const int bno = ((t >> 4) << 3) + (t & 7);
    const int bkg = (t >> 3) & 1;
    const int tq  = t >> 2, tr = t & 3;

    float acc[MT][2 * NT][4];
#pragma unroll
    for (int a = 0; a < MT; a++)
#pragma unroll
        for (int b = 0; b < 2 * NT; b++)
#pragma unroll
            for (int q = 0; q < 4; q++) acc[a][b][q] = 0.0f;

    uint4 areg[AIT];

    auto ldgA = [&](int ci) {
        const int kk = (ci % NCK) * 64;
#pragma unroll
        for (int it = 0; it < AIT; it++) {
            const int idx = tid + it * 256;
            const int r = idx >> 3, ch = idx & 7;
            areg[it] = *(const uint4*)(A + (size_t)(row0 + r) * K + kk + ch * 8);
        }
    };
    auto stsA = [&](int ci) {
        const int p = ci / NCK;
        const int s = ci % 3;
        const uint32_t off0 = 8192 + (uint32_t)s * STAGE;
#pragma unroll
        for (int it = 0; it < AIT; it++) {
            const int idx = tid + it * 256;
            const int r = idx >> 3, ch = idx & 7;
            uint4 v = areg[it];
            const __half hb = __float2half(blend_s[r * 8 + p]);
            __half2 hb2 = __half2half2(hb);
            const uint32_t b2 = *(uint32_t*)&hb2;
            v.x = hmul2u(v.x, b2);  v.y = hmul2u(v.y, b2);
            v.z = hmul2u(v.z, b2);  v.w = hmul2u(v.w, b2);
            *(uint4*)(smem + off0 + r * 128 + ((ch ^ (r & 7)) << 4)) = v;
        }
    };
    auto cpA = [&](int ci) {
        const int kk = (ci % NCK) * 64;
        const int s  = ci % 3;
        const uint32_t stA = sb + 8192 + (uint32_t)s * STAGE;
#pragma unroll
        for (int it = 0; it < AIT; it++) {
            const int idx = tid + it * 256;
            const int r = idx >> 3, ch = idx & 7;
            const __half* src = A + (size_t)(row0 + r) * K + kk + ch * 8;
            CP_ASYNC16(stA + r * 128 + ((ch ^ (r & 7)) << 4), src);
        }
    };
    auto cpB = [&](int ci) {
        const int p  = ci / NCK;
        const int kk = (ci % NCK) * 64;
        const int s  = ci % 3;
        const uint32_t stB = sb + 8192 + (uint32_t)s * STAGE + BM * 128;
#pragma unroll
        for (int it = 0; it < BIT_; it++) {
            const int idx = tid + it * 256;
            const int r = idx >> 3, ch = idx & 7;
            const __half* src = W + ((size_t)p * NTOT + n0 + r) * K + kk + ch * 8;
            CP_ASYNC16(stB + r * 128 + ((ch ^ (r & 7)) << 4), src);
        }
    };

    auto mmaStage = [&](int s) {
        const uint32_t stA = sb + 8192 + (uint32_t)s * STAGE;
        const uint32_t stB = stA + BM * 128;
#pragma unroll
        for (int kc = 0; kc < 4; kc++) {
            uint32_t a[MT][4];
#pragma unroll
            for (int mt = 0; mt < MT; mt++) {
                const int row = wm * (MT * 16) + mt * 16 + aro;
                const int ch = kc * 2 + akg;
                ldsm4(a[mt], stA + row * 128 + ((ch ^ (row & 7)) << 4));
            }
            uint32_t b[NT][4];
#pragma unroll
            for (int nt = 0; nt < NT; nt++) {
                const int n = wn * (NT * 16) + nt * 16 + bno;
                const int ch = kc * 2 + bkg;
                ldsm4(b[nt], stB + n * 128 + ((ch ^ (n & 7)) << 4));
            }
#pragma unroll
            for (int mt = 0; mt < MT; mt++)
#pragma unroll
                for (int nt = 0; nt < NT; nt++) {
                    mma16816(acc[mt][2 * nt + 0], a[mt], b[nt][0], b[nt][1]);
                    mma16816(acc[mt][2 * nt + 1], a[mt], b[nt][2], b[nt][3]);
                }
        }
    };

    // -------- pipeline: 3 stages --------
    if (NEXP == 1) { cpA(0); } else { ldgA(0); stsA(0); }
    cpB(0); CP_COMMIT();
    if (NCH > 1) {
        if (NEXP == 1) cpA(1); else ldgA(1);
        cpB(1);
    }
    CP_COMMIT();

#pragma unroll 1
    for (int ci = 0; ci < NCH; ci++) {
        CP_WAIT_1();
        __syncthreads();
        if (NEXP > 1 && ci + 1 < NCH) stsA(ci + 1);
        if (ci + 2 < NCH) {
            if (NEXP == 1) cpA(ci + 2); else ldgA(ci + 2);
            cpB(ci + 2);
        }
        CP_COMMIT();
        mmaStage(ci % 3);
    }

    // -------- epilogue --------
    float part[4][PEXP];
    if (EPI == 2) {
#pragma unroll
        for (int a = 0; a < 4; a++)
#pragma unroll
            for (int p = 0; p < PEXP; p++) part[a][p] = 0.0f;
    }
    const float2* gw2s2 = (const float2*)(smem + 4096);

#pragma unroll
    for (int mt = 0; mt < MT; mt++) {
#pragma unroll
        for (int h = 0; h < 2; h++) {
            const int r = wm * (MT * 16) + mt * 16 + tq + h * 8;
            float blv[PEXP];
            if (NEXP > 1) {
#pragma unroll
                for (int p = 0; p < PEXP; p++) blv[p] = blend_s[r * 8 + p];
            }
#pragma unroll
            for (int nn = 0; nn < 2 * NT; nn++) {
                const int col = wn * (NT * 16) + (nn >> 1) * 16 + (nn & 1) * 8 + tr * 2;
                float v0 = acc[mt][nn][h * 2 + 0];
                float v1 = acc[mt][nn][h * 2 + 1];
                if (NEXP == 1) {
                    v0 += bias_s[col]; v1 += bias_s[col + 1];
                } else {
                    float b0 = 0.0f, b1 = 0.0f;
#pragma unroll
                    for (int p = 0; p < PEXP; p++) {
                        b0 = fmaf(blv[p], bias_s[p * BN + col], b0);
                        b1 = fmaf(blv[p], bias_s[p * BN + col + 1], b1);
                    }
                    v0 += b0; v1 += b1;
                }
                if (EPI == 0) {
                    v0 = fmaxf(v0, 0.0f); v1 = fmaxf(v1, 0.0f);
                    __half2 hv = __floats2half2_rn(v0, v1);
                    *(uint32_t*)&Yh[(size_t)(row0 + r) * NTOT + n0 + col] = *(uint32_t*)&hv;
                } else if (EPI == 2) {
                    v0 = fmaxf(v0, 0.0f); v1 = fmaxf(v1, 0.0f);
                    const int a = mt * 2 + h;
#pragma unroll
                    for (int p = 0; p < PEXP; p++) {
                        const float2 g = gw2s2[p * 64 + (col >> 1)];
                        part[a][p] = fmaf(v0, g.x, fmaf(v1, g.y, part[a][p]));
                    }
                }
            }
        }
    }

    if (EPI == 2) {
#pragma unroll
        for (int a = 0; a < 4; a++)
#pragma unroll
            for (int p = 0; p < PEXP; p++) {
                part[a][p] += __shfl_xor_sync(0xffffffffu, part[a][p], 1);
                part[a][p] += __shfl_xor_sync(0xffffffffu, part[a][p], 2);
            }
        if (tr == 0) {
            const int j = blockIdx.x * 2 + wn;
#pragma unroll
            for (int a = 0; a < 4; a++) {
                const int grow = row0 + wm * (MT * 16) + (a >> 1) * 16 + (a & 1) * 8 + tq;
                float* dst = partOut + ((size_t)j * B_ + grow) * PEXP;
                *(float4*)dst       = make_float4(part[a][0], part[a][1], part[a][2], part[a][3]);
                *(float4*)(dst + 4) = make_float4(part[a][4], part[a][5], part[a][6], part[a][7]);
            }
        }
    }
}

// ======================= head GEMM (A resident in smem) ====================
// BM=64, BN=64, K=512, 8 experts. A tile (64x512 fp16 = 64KB) loaded ONCE;
// blend applied per-expert to A fragments in registers (hmul2 after ldsm).
// A-frag row map (m16n8k16): a0,a2 -> row tq ; a1,a3 -> row tq+8.
// smem PADDED past 114KB so only ONE CTA fits per SM -> 128 CTAs on 128 SMs.
__global__ __launch_bounds__(256, 1)
void head_gemm(const __half* __restrict__ A, const __half* __restrict__ W,
               const float* __restrict__ bias, const float* __restrict__ blend,
               float* __restrict__ Yf)
{
    constexpr int K = HIDD, BN = 64, NSTEP = PEXP * (K / 64);
    constexpr int OFF_A = 4096;            // bias 2KB + blend 2KB
    constexpr int OFF_B = OFF_A + 64 * 1024;

    extern __shared__ __align__(16) char smem[];
    float* bias_s  = (float*)smem;          // [8*64]
    float* blend_s = (float*)(smem + 2048); // [64*8]
    const uint32_t sb = smem_u32(smem);

    const int tid = threadIdx.x;
    const int wid = tid >> 5;
    const int t   = tid & 31;
    const int row0 = blockIdx.y * 64;

    for (int i = tid; i < PEXP * BN; i += 256) bias_s[i] = bias[i];
    for (int i = tid; i < 64 * 8; i += 256)
        blend_s[i] = blend[(size_t)(row0 + (i >> 3)) * PEXP + (i & 7)];
    __syncthreads();

    const int wm = wid >> 1, wn = wid & 1;
    const int aro = t & 15;
    const int akg = t >> 4;
    const int bno = ((t >> 4) << 3) + (t & 7);
    const int bkg = (t >> 3) & 1;
    const int tq  = t >> 2, tr = t & 3;

    // per-expert blend scalars for this thread's two A-frag rows
    uint32_t hbl[PEXP], hbh[PEXP];
    {
        const int r0 = wm * 16 + tq;
#pragma unroll
        for (int p = 0; p < PEXP; p++) {
            __half2 x = __half2half2(__float2half(blend_s[r0 * 8 + p]));
            __half2 y = __half2half2(__float2half(blend_s[(r0 + 8) * 8 + p]));
            hbl[p] = *(uint32_t*)&x;
            hbh[p] = *(uint32_t*)&y;
        }
    }

    float acc[4][4];
#pragma unroll
    for (int b = 0; b < 4; b++)
#pragma unroll
        for (int q = 0; q < 4; q++) acc[b][q] = 0.0f;

    // A: rows of 1024B; 128B sub-block per k-chunk, swizzle within sub-block
    auto cpA_all = [&]() {
#pragma unroll
        for (int it = 0; it < 16; it++) {
            const int idx = tid + it * 256;      // 4096 16B-chunks
            const int r = idx >> 6, c16 = idx & 63;
            const int c = c16 >> 3, ch8 = c16 & 7;
            const __half* src = A + (size_t)(row0 + r) * K + c16 * 8;
            CP_ASYNC16(sb + OFF_A + r * 1024 + c * 128 + ((ch8 ^ (r & 7)) << 4), src);
        }
    };
    auto cpB = [&](int ci) {
        const int p = ci & 7, kc64 = ci >> 3, s = ci % 3;
        const uint32_t stB = sb + OFF_B + (uint32_t)s * 8192;
#pragma unroll
        for (int it = 0; it < 2; it++) {
            const int idx = tid + it * 256;
            const int r = idx >> 3, ch = idx & 7;
            const __half* src = W + ((size_t)p * BN + r) * K + kc64 * 64 + ch * 8;
            CP_ASYNC16(stB + r * 128 + ((ch ^ (r & 7)) << 4), src);
        }
    };

    auto mmaStep = [&](int ci) {
        const int p = ci & 7, kc64 = ci >> 3, s = ci % 3;
        const uint32_t stA = sb + OFF_A;
        const uint32_t stB = sb + OFF_B + (uint32_t)s * 8192;
        const uint32_t h0 = hbl[p], h1 = hbh[p];
#pragma unroll
        for (int kc = 0; kc < 4; kc++) {
            uint32_t a[4], sa[4];
            const int row = wm * 16 + aro;
            const int ch = kc * 2 + akg;
            ldsm4(a, stA + row * 1024 + kc64 * 128 + ((ch ^ (row & 7)) << 4));
            // a0,a2 are row tq (h0); a1,a3 are row tq+8 (h1)
            sa[0] = hmul2u(a[0], h0);  sa[1] = hmul2u(a[1], h1);
            sa[2] = hmul2u(a[2], h0);  sa[3] = hmul2u(a[3], h1);
            uint32_t b[2][4];
#pragma unroll
            for (int nt = 0; nt < 2; nt++) {
                const int n = wn * 32 + nt * 16 + bno;
                const int chb = kc * 2 + bkg;
                ldsm4(b[nt], stB + n * 128 + ((chb ^ (n & 7)) << 4));
            }
            mma16816(acc[0], sa, b[0][0], b[0][1]);
            mma16816(acc[1], sa, b[0][2], b[0][3]);
            mma16816(acc[2], sa, b[1][0], b[1][1]);
            mma16816(acc[3], sa, b[1][2], b[1][3]);
        }
    };

    // pipeline: A + B0 in group 0; B1 in group 1; then 3-stage B ring
    cpA_all(); cpB(0); CP_COMMIT();
    cpB(1); CP_COMMIT();

#pragma unroll 1
    for (int ci = 0; ci < NSTEP; ci++) {
        CP_WAIT_1();
        __syncthreads();
        if (ci + 2 < NSTEP) cpB(ci + 2);
        CP_COMMIT();
        mmaStep(ci);
    }

    // -------- epilogue: blended bias + mu/std --------
#pragma unroll
    for (int h = 0; h < 2; h++) {
        const int r = wm * 16 + tq + h * 8;
        float blv[PEXP];
#pragma unroll
        for (int p = 0; p < PEXP; p++) blv[p] = blend_s[r * 8 + p];
#pragma unroll
        for (int nn = 0; nn < 4; nn++) {
            const int col = wn * 32 + (nn >> 1) * 16 + (nn & 1) * 8 + tr * 2;
            float v0 = acc[nn][h * 2 + 0];
            float v1 = acc[nn][h * 2 + 1];
            float b0 = 0.0f, b1 = 0.0f;
#pragma unroll
            for (int p = 0; p < PEXP; p++) {
                b0 = fmaf(blv[p], bias_s[p * BN + col], b0);
                b1 = fmaf(blv[p], bias_s[p * BN + col + 1], b1);
            }
            v0 += b0; v1 += b1;
            if (col >= 32)     v0 = expf(3.5f * tanhf(v0) - 1.5f);
            if (col + 1 >= 32) v1 = expf(3.5f * tanhf(v1) - 1.5f);
            *(float2*)&Yf[(size_t)(row0 + r) * BN + col] = make_float2(v0, v1);
        }
    }
}

// ======================= 8-partial sum + softmax ===========================
// 4 threads per row: each sums 2 of the 8 j-slices, 2 shfl combines, lane0 writes.
__global__ __launch_bounds__(256)
void softmax8(const float* __restrict__ part, const float* __restrict__ gb2,
              float* __restrict__ blend)
{
    const int gid  = blockIdx.x * 256 + threadIdx.x;   // 32768 threads
    const int row  = gid >> 2;
    const int quad = gid & 3;
    float l[PEXP];
#pragma unroll
    for (int p = 0; p < PEXP; p++) l[p] = 0.0f;
#pragma unroll
    for (int j = 0; j < 2; j++) {
        const int jj = quad * 2 + j;
        const float4* s = (const float4*)(part + ((size_t)jj * B_ + row) * PEXP);
        const float4 a = s[0], b = s[1];
        l[0] += a.x; l[1] += a.y; l[2] += a.z; l[3] += a.w;
        l[4] += b.x; l[5] += b.y; l[6] += b.z; l[7] += b.w;
    }
#pragma unroll
    for (int p = 0; p < PEXP; p++) {
        l[p] += __shfl_xor_sync(0xffffffffu, l[p], 1);
        l[p] += __shfl_xor_sync(0xffffffffu, l[p], 2);
    }

    float m = -1e30f;
#pragma unroll
    for (int p = 0; p < PEXP; p++) { l[p] += gb2[p]; m = fmaxf(m, l[p]); }
    float s = 0.0f;
#pragma unroll
    for (int p = 0; p < PEXP; p++) { l[p] = expf(l[p] - m); s += l[p]; }
    const float inv = 1.0f / s;
    if (quad == 0) {
        float4* dst = (float4*)(blend + (size_t)row * PEXP);
        dst[0] = make_float4(l[0] * inv, l[1] * inv, l[2] * inv, l[3] * inv);
        dst[1] = make_float4(l[4] * inv, l[5] * inv, l[6] * inv, l[7] * inv);
    }
}

// ======================= host launch =======================================
extern "C" void kernel_launch(void* const* d_in, const int* in_sizes, int n_in,
                              void* d_out, int out_size)
{
    const float* obs = (const float*)d_in[0];
    const float* gw0 = (const float*)d_in[1];
    const float* gb0 = (const float*)d_in[2];
    const float* gw1 = (const float*)d_in[3];
    const float* gb1 = (const float*)d_in[4];
    const float* gw2 = (const float*)d_in[5];
    const float* gb2 = (const float*)d_in[6];
    const float* ew0 = (const float*)d_in[7];
    const float* eb0 = (const float*)d_in[8];
    const float* ew1 = (const float*)d_in[9];
    const float* eb1 = (const float*)d_in[10];
    const float* ew2 = (const float*)d_in[11];
    const float* eb2 = (const float*)d_in[12];
    float* out = (float*)d_out;

    __half *obs16, *gw016, *gw116, *ew016, *ew116, *ew216;
    __half *act0, *actA, *actB;
    float *partb, *blend;
    cudaGetSymbolAddress((void**)&obs16, d_obs16);
    cudaGetSymbolAddress((void**)&gw016, d_gw016);
    cudaGetSymbolAddress((void**)&gw116, d_gw116);
    cudaGetSymbolAddress((void**)&ew016, d_ew016);
    cudaGetSymbolAddress((void**)&ew116, d_ew116);
    cudaGetSymbolAddress((void**)&ew216, d_ew216);
    cudaGetSymbolAddress((void**)&act0, d_act0);
    cudaGetSymbolAddress((void**)&actA, d_actA);
    cudaGetSymbolAddress((void**)&actB, d_actB);
    cudaGetSymbolAddress((void**)&partb, d_partbuf);
    cudaGetSymbolAddress((void**)&blend, d_blend);

    static const int S128  = 8192 + 3 * (128 * 128 + 128 * 128);   // 106496
    // head smem padded past 114KB so only ONE CTA fits per SM (128 CTAs -> 128 SMs)
    static const int SHEAD = 118784;
    cudaFuncSetAttribute(moe_gemm<1, 0, 128, 128, 256>, cudaFuncAttributeMaxDynamicSharedMemorySize, S128);
    cudaFuncSetAttribute(moe_gemm<1, 2, 128, 128, 512>, cudaFuncAttributeMaxDynamicSharedMemorySize, S128);
    cudaFuncSetAttribute(moe_gemm<8, 0, 128, 128, 256>, cudaFuncAttributeMaxDynamicSharedMemorySize, S128);
    cudaFuncSetAttribute(moe_gemm<8, 0, 128, 128, 512>, cudaFuncAttributeMaxDynamicSharedMemorySize, S128);
    cudaFuncSetAttribute(head_gemm, cudaFuncAttributeMaxDynamicSharedMemorySize, SHEAD);

    // -------- single batched convert --------
    CvtArgs ca;
    ca.src[0] = obs;  ca.dst[0] = obs16;
    ca.src[1] = gw0;  ca.dst[1] = gw016;
    ca.src[2] = gw1;  ca.dst[2] = gw116;
    ca.src[3] = ew0;  ca.dst[3] = ew016;
    ca.src[4] = ew1;  ca.dst[4] = ew116;
    ca.src[5] = ew2;  ca.dst[5] = ew216;
    int acc4 = 0;
    const int sizes4[6] = {B_ * OBSD / 4, HIDD * OBSD / 4, HIDD * HIDD / 4,
                           PEXP * HIDD * OBSD / 4, PEXP * HIDD * HIDD / 4,
                           PEXP * 2 * ACTD * HIDD / 4};
    for (int k = 0; k < 6; k++) { acc4 += sizes4[k]; ca.end[k] = acc4; }
    cvt_all<<<1024, 256>>>(ca, acc4);

    const dim3 blk(256);
    const dim3 g512(HIDD / 128, B_ / 128);   // (4, 64)
    // gate trunk; g1 fuses the gate-head logits into its epilogue
    moe_gemm<1, 0, 128, 128, 256><<<g512, blk, S128>>>(obs16, gw016, gb0, nullptr,
                                                       nullptr, nullptr, act0, nullptr, HIDD);
    moe_gemm<1, 2, 128, 128, 512><<<g512, blk, S128>>>(act0, gw116, gb1, nullptr,
                                                       gw2, partb, nullptr, nullptr, HIDD);
    softmax8<<<B_ * 4 / 256, blk>>>(partb, gb2, blend);
    // blended experts (blend folded into A operand)
    moe_gemm<8, 0, 128, 128, 256><<<g512, blk, S128>>>(obs16, ew016, eb0, blend,
                                                       nullptr, nullptr, actA, nullptr, HIDD);
    moe_gemm<8, 0, 128, 128, 512><<<g512, blk, S128>>>(actA, ew116, eb1, blend,
                                                       nullptr, nullptr, actB, nullptr, HIDD);
    // head: A-resident smem kernel, 128 CTAs on 128 distinct SMs (occ 1 via smem pad)
    head_gemm<<<dim3(1, B_ / 64), blk, SHEAD>>>(actB, ew216, eb2, blend, out);
}